// round 9
// baseline (speedup 1.0000x reference)
#include <cuda_runtime.h>
#include <cuda_bf16.h>

#define N_NODES 50000
#define N_EDGES 400000
#define N_GRAPHS 64
#define EDGE_GRID 148

typedef unsigned long long u64;

// Packed fp32x2 helpers (Blackwell FFMA2 path)
__device__ __forceinline__ u64 pack2(float a, float b) {
    u64 r; asm("mov.b64 %0,{%1,%2};" : "=l"(r) : "f"(a), "f"(b)); return r;
}
__device__ __forceinline__ u64 fma2(u64 a, u64 b, u64 c) {
    u64 d; asm("fma.rn.f32x2 %0,%1,%2,%3;" : "=l"(d) : "l"(a), "l"(b), "l"(c)); return d;
}
__device__ __forceinline__ float hadd2(u64 v) {
    float lo, hi; asm("mov.b64 {%0,%1},%2;" : "=f"(lo), "=f"(hi) : "l"(v)); return lo + hi;
}
__device__ __forceinline__ u64 relu2(u64 v) {
    float lo, hi; asm("mov.b64 {%0,%1},%2;" : "=f"(lo), "=f"(hi) : "l"(v));
    return pack2(fmaxf(lo, 0.f), fmaxf(hi, 0.f));
}

// Scratch (device globals; no allocation allowed)
__device__ float g_buf1[N_NODES * 32];   // conv1 accumulator (pre-relu)
__device__ float g_buf2[N_NODES * 16];   // conv2 accumulator
__device__ float g_pool[N_GRAPHS * 16];  // pooled graph features

// ---------------------------------------------------------------------------
// K1: agg1[n,o] = c1_bias[o] + sum_i x[n,i] * c1_root[i,o]
// ---------------------------------------------------------------------------
__global__ void node_init1(const float* __restrict__ x,
                           const float* __restrict__ root,
                           const float* __restrict__ bias) {
    int t = blockIdx.x * blockDim.x + threadIdx.x;
    if (t >= N_NODES * 32) return;
    int n = t >> 5, o = t & 31;
    const float* xr = x + n * 16;
    float acc = bias[o];
#pragma unroll
    for (int i = 0; i < 16; i++) acc = fmaf(xr[i], root[i * 32 + o], acc);
    g_buf1[t] = acc;
}

// ---------------------------------------------------------------------------
// K2: conv1 edge kernel. Persistent; warp = 8 edges; lane = out channel (32).
// x rows gathered cooperatively into SMEM at iteration top; gather indices
// re-loaded directly from ei (L1 hit) — no dynamic register indexing.
// ---------------------------------------------------------------------------
__global__ __launch_bounds__(256, 1) void edge1(
    const float* __restrict__ x, const int* __restrict__ ei,
    const float* __restrict__ ea,
    const float* __restrict__ w1, const float* __restrict__ b1,
    const float* __restrict__ w2, const float* __restrict__ b2) {
    extern __shared__ u64 sm[];
    u64* s_w2p = sm;                       // 32*8*32 = 8192
    u64* s_b2p = sm + 8192;                // 256
    u64* s_hA  = sm + 8448;                // 8 warps * 264 = 2112
    u64* s_xA  = sm + 10560;               // 8 warps * 64  = 512
    float* s_w1 = (float*)(sm + 11072);    // 256 floats (128 u64)
    float* s_b1 = (float*)(sm + 11200);    // 32 floats (16 u64)
    // total 11216 u64 = 89728 B

    int tid = threadIdx.x;
    for (int idx = tid; idx < 8192; idx += 256) {
        int k = idx >> 8, r = idx & 255;
        int ip = r >> 5, o = r & 31;
        s_w2p[idx] = pack2(w2[k * 512 + ip * 64 + o], w2[k * 512 + ip * 64 + 32 + o]);
    }
    {
        int ip = tid >> 5, o = tid & 31;
        s_b2p[tid] = pack2(b2[ip * 64 + o], b2[ip * 64 + 32 + o]);
        s_w1[tid] = w1[tid];
    }
    if (tid < 32) s_b1[tid] = b1[tid];
    __syncthreads();

    int warp = tid >> 5, lane = tid & 31;
    u64* sh = s_hA + warp * 264;
    u64* sx = s_xA + warp * 64;

    const long NG = N_EDGES / 8;
    const long stride = (long)EDGE_GRID * 8;

    for (long g = (long)blockIdx.x * 8 + warp; g < NG; g += stride) {
        long e0 = g * 8;
        // dst indices into registers (static indexing only)
        int dsts[8];
#pragma unroll
        for (int e = 0; e < 8; e++) dsts[e] = __ldg(ei + N_EDGES + e0 + e);
        // cooperative x-gather: lane covers words lane, lane+32; index loaded
        // directly (same 32B sector for all lanes -> L1 broadcast)
#pragma unroll
        for (int j = 0; j < 2; j++) {
            int w = lane + 32 * j;
            int e = w >> 3, ip = w & 7;
            int src = __ldg(ei + e0 + e);
            sx[w] = __ldg((const u64*)x + (long)src * 8 + ip);
        }
        // edge-MLP (direct ea loads, R3-proven)
#pragma unroll
        for (int e = 0; e < 8; e++) {
            const float4* ear = (const float4*)(ea + (e0 + e) * 8);
            float4 a0 = __ldg(ear), a1 = __ldg(ear + 1);
            float acc = s_b1[lane];
            acc = fmaf(a0.x, s_w1[0 * 32 + lane], acc);
            acc = fmaf(a0.y, s_w1[1 * 32 + lane], acc);
            acc = fmaf(a0.z, s_w1[2 * 32 + lane], acc);
            acc = fmaf(a0.w, s_w1[3 * 32 + lane], acc);
            acc = fmaf(a1.x, s_w1[4 * 32 + lane], acc);
            acc = fmaf(a1.y, s_w1[5 * 32 + lane], acc);
            acc = fmaf(a1.z, s_w1[6 * 32 + lane], acc);
            acc = fmaf(a1.w, s_w1[7 * 32 + lane], acc);
            acc = fmaxf(acc, 0.f);
            sh[e * 33 + lane] = pack2(acc, acc);
        }
        __syncwarp();

        // mainloop: acc init from b2 pairs (algebra-equivalent to bias row)
        u64 acc[8][8];
#pragma unroll
        for (int ip = 0; ip < 8; ip++) {
            u64 b = s_b2p[ip * 32 + lane];
#pragma unroll
            for (int e = 0; e < 8; e++) acc[e][ip] = b;
        }
#pragma unroll 2
        for (int k = 0; k < 32; k++) {
            u64 h[8];
#pragma unroll
            for (int e = 0; e < 8; e++) h[e] = sh[e * 33 + k];
            const u64* wr = s_w2p + k * 256 + lane;
#pragma unroll
            for (int ip = 0; ip < 8; ip++) {
                u64 w = wr[ip * 32];
#pragma unroll
                for (int e = 0; e < 8; e++) acc[e][ip] = fma2(h[e], w, acc[e][ip]);
            }
        }
        __syncwarp();

        // epilogue: contract with staged x, scatter-add
#pragma unroll
        for (int e = 0; e < 8; e++) {
            u64 s = 0ull;
#pragma unroll
            for (int ip = 0; ip < 8; ip++) s = fma2(sx[e * 8 + ip], acc[e][ip], s);
            atomicAdd(&g_buf1[(long)dsts[e] * 32 + lane], hadd2(s));
        }
        __syncwarp();  // protect sx before next iteration's overwrite
    }
}

// ---------------------------------------------------------------------------
// K4: agg2[n,o] = c2_bias[o] + sum_i relu(agg1[n,i]) * c2_root[i,o]
// ---------------------------------------------------------------------------
__global__ void node_init2(const float* __restrict__ root,
                           const float* __restrict__ bias) {
    int t = blockIdx.x * blockDim.x + threadIdx.x;
    if (t >= N_NODES * 16) return;
    int n = t >> 4, o = t & 15;
    const float* xr = g_buf1 + n * 32;
    float acc = bias[o];
#pragma unroll
    for (int i = 0; i < 32; i++) acc = fmaf(fmaxf(xr[i], 0.f), root[i * 16 + o], acc);
    g_buf2[t] = acc;
}

// ---------------------------------------------------------------------------
// K5: conv2 edge kernel. Persistent; warp = 8 edges; half-warp sub owns 4.
// h1 rows gathered cooperatively (relu fused); gather indices loaded direct.
// ---------------------------------------------------------------------------
__global__ __launch_bounds__(256, 1) void edge2(
    const int* __restrict__ ei, const float* __restrict__ ea,
    const float* __restrict__ w1, const float* __restrict__ b1,
    const float* __restrict__ w2, const float* __restrict__ b2) {
    extern __shared__ u64 sm[];
    u64* s_w2p = sm;                       // 32*16*16 = 8192
    u64* s_b2p = sm + 8192;                // 256
    u64* s_hA  = sm + 8448;                // 2112
    u64* s_xA  = sm + 10560;               // 8 warps * 128 = 1024
    float* s_w1 = (float*)(sm + 11584);    // 256 floats (128 u64)
    float* s_b1 = (float*)(sm + 11712);    // 32 floats (16 u64)
    // total 11728 u64 = 93824 B

    int tid = threadIdx.x;
    for (int idx = tid; idx < 8192; idx += 256) {
        int k = idx >> 8, r = idx & 255;
        int ip = r >> 4, o = r & 15;
        s_w2p[idx] = pack2(w2[k * 512 + ip * 32 + o], w2[k * 512 + ip * 32 + 16 + o]);
    }
    {
        int ip = tid >> 4, o = tid & 15;
        s_b2p[tid] = pack2(b2[ip * 32 + o], b2[ip * 32 + 16 + o]);
        s_w1[tid] = w1[tid];
    }
    if (tid < 32) s_b1[tid] = b1[tid];
    __syncthreads();

    int warp = tid >> 5, lane = tid & 31;
    int sub = lane >> 4, o = lane & 15;
    u64* sh = s_hA + warp * 264;
    u64* sx = s_xA + warp * 128;

    const long NG = N_EDGES / 8;
    const long stride = (long)EDGE_GRID * 8;

    for (long g = (long)blockIdx.x * 8 + warp; g < NG; g += stride) {
        long e0 = g * 8;
        int dsts[4];
#pragma unroll
        for (int t2 = 0; t2 < 4; t2++)
            dsts[t2] = __ldg(ei + N_EDGES + e0 + sub * 4 + t2);
        // cooperative h1-gather (relu fused): lane covers words lane+32j
#pragma unroll
        for (int j = 0; j < 4; j++) {
            int w = lane + 32 * j;
            int e = w >> 4, ip = w & 15;
            int src = __ldg(ei + e0 + e);
            sx[w] = relu2(__ldg((const u64*)g_buf1 + (long)src * 16 + ip));
        }
        // edge-MLP
#pragma unroll
        for (int e = 0; e < 8; e++) {
            const float4* ear = (const float4*)(ea + (e0 + e) * 8);
            float4 a0 = __ldg(ear), a1 = __ldg(ear + 1);
            float acc = s_b1[lane];
            acc = fmaf(a0.x, s_w1[0 * 32 + lane], acc);
            acc = fmaf(a0.y, s_w1[1 * 32 + lane], acc);
            acc = fmaf(a0.z, s_w1[2 * 32 + lane], acc);
            acc = fmaf(a0.w, s_w1[3 * 32 + lane], acc);
            acc = fmaf(a1.x, s_w1[4 * 32 + lane], acc);
            acc = fmaf(a1.y, s_w1[5 * 32 + lane], acc);
            acc = fmaf(a1.z, s_w1[6 * 32 + lane], acc);
            acc = fmaf(a1.w, s_w1[7 * 32 + lane], acc);
            acc = fmaxf(acc, 0.f);
            sh[e * 33 + lane] = pack2(acc, acc);
        }
        __syncwarp();

        // mainloop
        u64 acc[4][16];
#pragma unroll
        for (int ip = 0; ip < 16; ip++) {
            u64 b = s_b2p[ip * 16 + o];
#pragma unroll
            for (int t2 = 0; t2 < 4; t2++) acc[t2][ip] = b;
        }
#pragma unroll 2
        for (int k = 0; k < 32; k++) {
            u64 h[4];
#pragma unroll
            for (int t2 = 0; t2 < 4; t2++) h[t2] = sh[(sub * 4 + t2) * 33 + k];
            const u64* wr = s_w2p + k * 256 + o;
#pragma unroll
            for (int ip = 0; ip < 16; ip++) {
                u64 w = wr[ip * 16];
#pragma unroll
                for (int t2 = 0; t2 < 4; t2++) acc[t2][ip] = fma2(h[t2], w, acc[t2][ip]);
            }
        }
        __syncwarp();

        // epilogue
#pragma unroll
        for (int t2 = 0; t2 < 4; t2++) {
            int e = sub * 4 + t2;
            u64 s = 0ull;
#pragma unroll
            for (int ip = 0; ip < 16; ip++) s = fma2(sx[e * 16 + ip], acc[t2][ip], s);
            atomicAdd(&g_buf2[(long)dsts[t2] * 16 + o], hadd2(s));
        }
        __syncwarp();  // protect sx before next iteration's overwrite
    }
}

// ---------------------------------------------------------------------------
// K6a: zero pooled buffer
// ---------------------------------------------------------------------------
__global__ void zero_pool(void) {
    int t = blockIdx.x * blockDim.x + threadIdx.x;
    if (t < N_GRAPHS * 16) g_pool[t] = 0.f;
}

// ---------------------------------------------------------------------------
// K6: relu(agg2) + global_add_pool via per-block shared accumulation
// ---------------------------------------------------------------------------
__global__ void pool_kernel(const int* __restrict__ batch) {
    __shared__ float sg[N_GRAPHS * 16];
    int tid = threadIdx.x;
    for (int i = tid; i < N_GRAPHS * 16; i += blockDim.x) sg[i] = 0.f;
    __syncthreads();
    int t = blockIdx.x * blockDim.x + tid;
    int stride = gridDim.x * blockDim.x;
    for (int n = t; n < N_NODES; n += stride) {
        int b = batch[n];
        const float* r = g_buf2 + n * 16;
#pragma unroll
        for (int f = 0; f < 16; f++)
            atomicAdd(&sg[b * 16 + f], fmaxf(r[f], 0.f));
    }
    __syncthreads();
    for (int i = tid; i < N_GRAPHS * 16; i += blockDim.x)
        if (sg[i] != 0.f) atomicAdd(&g_pool[i], sg[i]);
}

// ---------------------------------------------------------------------------
// K7: head — per-graph MLP
// ---------------------------------------------------------------------------
__global__ void head_kernel(const float* __restrict__ fc1_w,
                            const float* __restrict__ fc1_b,
                            const float* __restrict__ out_w,
                            const float* __restrict__ out_b,
                            float* __restrict__ out) {
    int t = threadIdx.x;
    if (t >= N_GRAPHS) return;
    const float* gr = g_pool + t * 16;
    float r = out_b[0];
#pragma unroll
    for (int o = 0; o < 32; o++) {
        float acc = fc1_b[o];
#pragma unroll
        for (int i = 0; i < 16; i++) acc = fmaf(gr[i], fc1_w[i * 32 + o], acc);
        r = fmaf(fmaxf(acc, 0.f), out_w[o], r);
    }
    out[t] = r;
}

// ---------------------------------------------------------------------------
extern "C" void kernel_launch(void* const* d_in, const int* in_sizes, int n_in,
                              void* d_out, int out_size) {
    const float* x        = (const float*)d_in[0];
    const int*   ei       = (const int*)  d_in[1];
    const float* ea       = (const float*)d_in[2];
    const int*   batch    = (const int*)  d_in[3];
    const float* c1_w1    = (const float*)d_in[4];
    const float* c1_b1    = (const float*)d_in[5];
    const float* c1_w2    = (const float*)d_in[6];
    const float* c1_b2    = (const float*)d_in[7];
    const float* c1_root  = (const float*)d_in[8];
    const float* c1_bias  = (const float*)d_in[9];
    const float* c2_w1    = (const float*)d_in[10];
    const float* c2_b1    = (const float*)d_in[11];
    const float* c2_w2    = (const float*)d_in[12];
    const float* c2_b2    = (const float*)d_in[13];
    const float* c2_root  = (const float*)d_in[14];
    const float* c2_bias  = (const float*)d_in[15];
    const float* fc1_w    = (const float*)d_in[16];
    const float* fc1_b    = (const float*)d_in[17];
    const float* out_w    = (const float*)d_in[18];
    const float* out_b    = (const float*)d_in[19];
    float* out = (float*)d_out;

    const int smem_e1 = 11216 * 8;   // 89728 B
    const int smem_e2 = 11728 * 8;   // 93824 B
    cudaFuncSetAttribute(edge1, cudaFuncAttributeMaxDynamicSharedMemorySize, smem_e1);
    cudaFuncSetAttribute(edge2, cudaFuncAttributeMaxDynamicSharedMemorySize, smem_e2);

    // conv1
    node_init1<<<(N_NODES * 32 + 255) / 256, 256>>>(x, c1_root, c1_bias);
    edge1<<<EDGE_GRID, 256, smem_e1>>>(x, ei, ea, c1_w1, c1_b1, c1_w2, c1_b2);
    // conv2 (relu fused into consumers of g_buf1)
    node_init2<<<(N_NODES * 16 + 255) / 256, 256>>>(c2_root, c2_bias);
    edge2<<<EDGE_GRID, 256, smem_e2>>>(ei, ea, c2_w1, c2_b1, c2_w2, c2_b2);
    // pool + head
    zero_pool<<<1, 1024>>>();
    pool_kernel<<<120, 256>>>(batch);
    head_kernel<<<1, 64>>>(fc1_w, fc1_b, out_w, out_b, out);
}